// round 1
// baseline (speedup 1.0000x reference)
#include <cuda_runtime.h>

// ---------------------------------------------------------------------------
// BrickVectorEdgeModel: fused fp32 baseline
//   stage1: f1 = relu(brick@Wa^T + b_a + xy@Wxy^T + b_xy)
//           f2 = relu(f1@Wb^T + b_b)
//           u  = f2@W1^T   (W1 = W_ca[:, :512])
//           v  = f2@W2^T   (W2 = W_ca[:, 512:])
//   stage2 (per (b,i,j)): e0 = relu(v[b,i] + u[b,j] + b_ca)
//           e1 = relu(e0@Wcb^T + b_cb); e2 = relu(e1@Wcc^T + b_cc)
//           out[b,i,j,:] = e2@Wout^T + b_out
// All math fp32 (fma.rn.f32x2 packed pipe). No e materialization in HBM.
// ---------------------------------------------------------------------------

#define NROWS 768           // B*N = 4*192
#define HDIM  512

__device__ float g_u[NROWS * HDIM];   // 1.5 MB scratch
__device__ float g_v[NROWS * HDIM];

// ---- packed fp32x2 helpers (sm_103a) --------------------------------------
__device__ __forceinline__ unsigned long long pack2(float x, float y) {
    unsigned long long r;
    asm("mov.b64 %0, {%1, %2};" : "=l"(r) : "f"(x), "f"(y));
    return r;
}
__device__ __forceinline__ void ffma2(unsigned long long& d,
                                      unsigned long long a,
                                      unsigned long long b) {
    asm("fma.rn.f32x2 %0, %1, %2, %0;" : "+l"(d) : "l"(a), "l"(b));
}
__device__ __forceinline__ float2 unpack2(unsigned long long v) {
    float2 f;
    asm("mov.b64 {%0, %1}, %2;" : "=f"(f.x), "=f"(f.y) : "l"(v));
    return f;
}

// ---------------------------------------------------------------------------
// layer512: OUT[m][c] = act( sum_k IN[m][k] * Wg[c*wstride + k] (+ bias[c]) )
//   IN  : smem [M][512]
//   Wg  : global, row-major, row stride wstride
//   OUT : smem or global, row stride ostride
//   wt  : smem scratch 128*36 floats
// 256 threads. Warp layout: 4 row groups x 2 col halves.
// Accumulate k-even/odd packed in f32x2, sum halves at epilogue.
// ---------------------------------------------------------------------------
template <int M, bool RELU, bool BIAS>
__device__ __forceinline__ void layer512(const float* __restrict__ in,
                                         const float* __restrict__ Wg,
                                         int wstride,
                                         const float* __restrict__ bias,
                                         float* __restrict__ out,
                                         int ostride,
                                         float* __restrict__ wt) {
    const int tid  = threadIdx.x;
    const int lane = tid & 31;
    const int warp = tid >> 5;
    const int ch   = warp & 1;       // column half (64 cols each)
    const int rg   = warp >> 1;      // row group 0..3
    constexpr int RPW = M / 4;       // rows per warp
    const int rbase = rg * RPW;

    for (int nt = 0; nt < 4; ++nt) {          // 4 column tiles of 128
        unsigned long long acc[RPW][2];
#pragma unroll
        for (int rr = 0; rr < RPW; ++rr) {
            acc[rr][0] = 0ull;
            acc[rr][1] = 0ull;
        }

        for (int kt = 0; kt < 16; ++kt) {     // 16 k tiles of 32
            __syncthreads();                  // wt reuse / producer visibility
            // load W tile [128 cols][32 k] -> wt[c*36 + k] (pad 36)
#pragma unroll
            for (int s = 0; s < 4; ++s) {
                int idx = tid + s * 256;      // 0..1023 float4 slots
                int c   = idx >> 3;
                int k4  = (idx & 7) * 4;
                float4 w = *(const float4*)&Wg[(nt * 128 + c) * wstride +
                                               kt * 32 + k4];
                *(float4*)&wt[c * 36 + k4] = w;
            }
            __syncthreads();

            const float* inb = in + kt * 32;
#pragma unroll
            for (int kk = 0; kk < 32; kk += 4) {
                unsigned long long w01[2], w23[2];
#pragma unroll
                for (int cc = 0; cc < 2; ++cc) {
                    int cl = ch * 64 + cc * 32 + lane;
                    float4 w = *(const float4*)&wt[cl * 36 + kk];
                    w01[cc] = pack2(w.x, w.y);
                    w23[cc] = pack2(w.z, w.w);
                }
#pragma unroll
                for (int rr = 0; rr < RPW; ++rr) {
                    float4 a = *(const float4*)&inb[(rbase + rr) * 512 + kk];
                    unsigned long long a01 = pack2(a.x, a.y);
                    unsigned long long a23 = pack2(a.z, a.w);
#pragma unroll
                    for (int cc = 0; cc < 2; ++cc) {
                        ffma2(acc[rr][cc], a01, w01[cc]);
                        ffma2(acc[rr][cc], a23, w23[cc]);
                    }
                }
            }
        }

        // epilogue
#pragma unroll
        for (int cc = 0; cc < 2; ++cc) {
            int c = nt * 128 + ch * 64 + cc * 32 + lane;
            float bval = BIAS ? bias[c] : 0.0f;
#pragma unroll
            for (int rr = 0; rr < RPW; ++rr) {
                float2 s = unpack2(acc[rr][cc]);
                float r  = s.x + s.y + bval;
                if (RELU) r = fmaxf(r, 0.0f);
                out[(rbase + rr) * ostride + c] = r;
            }
        }
    }
}

// ---------------------------------------------------------------------------
// Stage 1: 96 CTAs x 8 rows -> g_u, g_v
// ---------------------------------------------------------------------------
__global__ void __launch_bounds__(256, 1)
stage1_kernel(const float* __restrict__ brick, const float* __restrict__ xy,
              const float* __restrict__ Wxy,   const float* __restrict__ bxy,
              const float* __restrict__ Wa,    const float* __restrict__ ba,
              const float* __restrict__ Wb,    const float* __restrict__ bb,
              const float* __restrict__ Wca) {
    extern __shared__ float sm[];
    float* A  = sm;                    // [8][512]
    float* Bm = sm + 8 * 512;          // [8][512]
    float* wt = sm + 16 * 512;         // [128][36]

    const int r0 = blockIdx.x * 8;

    // load brick rows
    for (int idx = threadIdx.x; idx < 8 * 128; idx += 256) {
        int m = idx >> 7, q = idx & 127;
        *(float4*)&A[m * 512 + q * 4] =
            *(const float4*)&brick[(size_t)(r0 + m) * 512 + q * 4];
    }

    // f1 pre-activation with b_a
    layer512<8, false, true>(A, Wa, 512, ba, Bm, 512, wt);
    __syncthreads();
    // add xy path + b_xy, relu
    for (int idx = threadIdx.x; idx < 8 * 512; idx += 256) {
        int m = idx >> 9, h = idx & 511;
        float x0 = xy[(r0 + m) * 2 + 0];
        float x1 = xy[(r0 + m) * 2 + 1];
        float val = Bm[idx] + x0 * Wxy[h * 2 + 0] + x1 * Wxy[h * 2 + 1] + bxy[h];
        Bm[idx] = fmaxf(val, 0.0f);
    }

    // f2
    layer512<8, true, true>(Bm, Wb, 512, bb, A, 512, wt);
    // u = f2 @ W_ca[:, :512]^T ; v = f2 @ W_ca[:, 512:]^T
    layer512<8, false, false>(A, Wca, 1024, nullptr, g_u + r0 * 512, 512, wt);
    layer512<8, false, false>(A, Wca + 512, 1024, nullptr, g_v + r0 * 512, 512, wt);
}

// ---------------------------------------------------------------------------
// Stage 2: fused pairwise edge MLP. Grid (6 jtiles, 192 i, 4 b), 32 pairs/CTA.
// ---------------------------------------------------------------------------
__global__ void __launch_bounds__(256, 1)
pair_kernel(const float* __restrict__ bca,
            const float* __restrict__ Wcb, const float* __restrict__ bcb,
            const float* __restrict__ Wcc, const float* __restrict__ bcc,
            const float* __restrict__ Wout, const float* __restrict__ bout,
            float* __restrict__ out) {
    extern __shared__ float sm[];
    float* E0   = sm;                       // [32][512]
    float* E1   = sm + 16384;               // [32][512]
    float* wt   = sm + 32768;               // [128][36]
    float* vrow = sm + 32768 + 4608;        // [512]

    const int j0 = blockIdx.x * 32;
    const int i  = blockIdx.y;
    const int b  = blockIdx.z;

    // v row for this (b, i)
    const float* vg = g_v + (size_t)(b * 192 + i) * 512;
    for (int q = threadIdx.x; q < 128; q += 256)
        *(float4*)&vrow[q * 4] = *(const float4*)&vg[q * 4];
    __syncthreads();

    // e0[m][h] = relu(v[b,i,h] + u[b,j0+m,h] + b_ca[h])
    for (int idx = threadIdx.x; idx < 32 * 128; idx += 256) {
        int m = idx >> 7, q = idx & 127;
        int h = q * 4;
        float4 u4 = *(const float4*)&g_u[(size_t)(b * 192 + j0 + m) * 512 + h];
        float4 v4 = *(const float4*)&vrow[h];
        float4 c4 = *(const float4*)&bca[h];
        float4 e;
        e.x = fmaxf(u4.x + v4.x + c4.x, 0.0f);
        e.y = fmaxf(u4.y + v4.y + c4.y, 0.0f);
        e.z = fmaxf(u4.z + v4.z + c4.z, 0.0f);
        e.w = fmaxf(u4.w + v4.w + c4.w, 0.0f);
        *(float4*)&E0[m * 512 + h] = e;
    }

    layer512<32, true, true>(E0, Wcb, 512, bcb, E1, 512, wt);
    layer512<32, true, true>(E1, Wcc, 512, bcc, E0, 512, wt);
    __syncthreads();

    // output head: out[b,i,j,o] = e2 . Wout[o] + bout[o]
    const int warp = threadIdx.x >> 5;
    const int lane = threadIdx.x & 31;
#pragma unroll
    for (int rr = 0; rr < 4; ++rr) {
        int r = warp * 4 + rr;
        float s0 = 0.0f, s1 = 0.0f;
        for (int h = lane; h < 512; h += 32) {
            float f = E0[r * 512 + h];
            s0 += f * Wout[h];
            s1 += f * Wout[512 + h];
        }
#pragma unroll
        for (int off = 16; off; off >>= 1) {
            s0 += __shfl_down_sync(0xffffffffu, s0, off);
            s1 += __shfl_down_sync(0xffffffffu, s1, off);
        }
        if (lane == 0) {
            size_t o = ((size_t)(b * 192 + i) * 192 + (j0 + r)) * 2;
            out[o]     = s0 + bout[0];
            out[o + 1] = s1 + bout[1];
        }
    }
}

// ---------------------------------------------------------------------------
extern "C" void kernel_launch(void* const* d_in, const int* in_sizes, int n_in,
                              void* d_out, int out_size) {
    const float* brick = (const float*)d_in[0];
    const float* xy    = (const float*)d_in[1];
    const float* Wxy   = (const float*)d_in[2];
    const float* bxy   = (const float*)d_in[3];
    const float* Wa    = (const float*)d_in[4];
    const float* ba    = (const float*)d_in[5];
    const float* Wb    = (const float*)d_in[6];
    const float* bb    = (const float*)d_in[7];
    const float* Wca   = (const float*)d_in[8];
    const float* bca   = (const float*)d_in[9];
    const float* Wcb   = (const float*)d_in[10];
    const float* bcb   = (const float*)d_in[11];
    const float* Wcc   = (const float*)d_in[12];
    const float* bcc   = (const float*)d_in[13];
    const float* Wout  = (const float*)d_in[14];
    const float* bout  = (const float*)d_in[15];
    float* out = (float*)d_out;

    const size_t s1 = (size_t)(8 * 512 + 8 * 512 + 128 * 36) * sizeof(float);
    const size_t s2 = (size_t)(32 * 512 + 32 * 512 + 128 * 36 + 512) * sizeof(float);

    cudaFuncSetAttribute(stage1_kernel,
                         cudaFuncAttributeMaxDynamicSharedMemorySize, (int)s1);
    cudaFuncSetAttribute(pair_kernel,
                         cudaFuncAttributeMaxDynamicSharedMemorySize, (int)s2);

    stage1_kernel<<<96, 256, s1>>>(brick, xy, Wxy, bxy, Wa, ba, Wb, bb, Wca);

    dim3 grid(6, 192, 4);
    pair_kernel<<<grid, 256, s2>>>(bca, Wcb, bcb, Wcc, bcc, Wout, bout, out);
}

// round 6
// speedup vs baseline: 2.9922x; 2.9922x over previous
#include <cuda_runtime.h>
#include <cuda_bf16.h>
#include <cstdint>

// ===========================================================================
// BrickVectorEdgeModel — mma.sync bf16-split version (sm_103 family target;
// tcgen05 rejected by ptxas => use family-common HMMA path)
//   stage1 (SIMT fp32): u, v
//   prep:   split Wcb/Wcc into bf16 hi/lo, permuted-row blobs
//   layer1: e0 = relu(v_i + u_j + b_ca) built in smem (bf16 hi/lo);
//           e1 = relu(e0@Wcb^T + b_cb) via mma.sync 3-term split ->
//           global permuted hi/lo blobs
//   layer2: e2 = relu(e1@Wcc^T + b_cc) via mma.sync; fused @W_out + b_out
// ===========================================================================

#define HD 512
#define TILE_M 64
#define N_TILES2 2304          // 147456 / 64

__device__ float g_u[768 * HD];
__device__ float g_v[768 * HD];
__device__ char  g_wcb_hi[524288];
__device__ char  g_wcb_lo[524288];
__device__ char  g_wcc_hi[524288];
__device__ char  g_wcc_lo[524288];
__device__ char  g_e1_hi[150994944];   // 2304 tiles * 64 rows * 1024B
__device__ char  g_e1_lo[150994944];

extern __shared__ char s_raw[];

// ---------------- PTX helpers ----------------------------------------------
__device__ __forceinline__ uint32_t smem_u32(const void* p) {
    uint32_t a;
    asm("{ .reg .u64 t; cvta.to.shared.u64 t, %1; cvt.u32.u64 %0, t; }"
        : "=r"(a) : "l"(p));
    return a;
}
__device__ __forceinline__ void cp16(uint32_t d, const void* s) {
    asm volatile("cp.async.cg.shared.global [%0], [%1], 16;" :: "r"(d), "l"(s));
}
__device__ __forceinline__ void cp_commit() { asm volatile("cp.async.commit_group;"); }
__device__ __forceinline__ void cp_wait1()  { asm volatile("cp.async.wait_group 1;"); }
__device__ __forceinline__ void cp_wait0()  { asm volatile("cp.async.wait_group 0;"); }

__device__ __forceinline__ void ldsm_x4(uint32_t* r, uint32_t a) {
    asm volatile("ldmatrix.sync.aligned.m8n8.x4.shared.b16 {%0,%1,%2,%3}, [%4];"
                 : "=r"(r[0]), "=r"(r[1]), "=r"(r[2]), "=r"(r[3]) : "r"(a));
}
__device__ __forceinline__ void mma16816(float* d, const uint32_t* a,
                                         const uint32_t* b) {
    asm volatile("mma.sync.aligned.m16n8k16.row.col.f32.bf16.bf16.f32 "
                 "{%0,%1,%2,%3}, {%4,%5,%6,%7}, {%8,%9}, {%0,%1,%2,%3};"
                 : "+f"(d[0]), "+f"(d[1]), "+f"(d[2]), "+f"(d[3])
                 : "r"(a[0]), "r"(a[1]), "r"(a[2]), "r"(a[3]),
                   "r"(b[0]), "r"(b[1]));
}
__device__ __forceinline__ uint32_t pkbf(__nv_bfloat16 a, __nv_bfloat16 b) {
    return (uint32_t)__bfloat16_as_ushort(a) |
           ((uint32_t)__bfloat16_as_ushort(b) << 16);
}

// permuted row layout: 1024B rows, 16B chunks, chunk ^= (row & 7)
__device__ __forceinline__ uint32_t prow(int row, int chunk) {
    return (uint32_t)(row * 1024 + ((chunk ^ (row & 7)) << 4));
}

// ---------------- stage 1: SIMT fp32 (validated R1) ------------------------
__device__ __forceinline__ unsigned long long pack2(float x, float y) {
    unsigned long long r;
    asm("mov.b64 %0, {%1, %2};" : "=l"(r) : "f"(x), "f"(y));
    return r;
}
__device__ __forceinline__ void ffma2(unsigned long long& d,
                                      unsigned long long a, unsigned long long b) {
    asm("fma.rn.f32x2 %0, %1, %2, %0;" : "+l"(d) : "l"(a), "l"(b));
}
__device__ __forceinline__ float2 unpack2(unsigned long long v) {
    float2 f;
    asm("mov.b64 {%0, %1}, %2;" : "=f"(f.x), "=f"(f.y) : "l"(v));
    return f;
}

template <int M, bool RELU, bool BIAS>
__device__ __forceinline__ void layer512(const float* __restrict__ in,
                                         const float* __restrict__ Wg, int wstride,
                                         const float* __restrict__ bias,
                                         float* __restrict__ out, int ostride,
                                         float* __restrict__ wt) {
    const int tid = threadIdx.x, lane = tid & 31, warp = tid >> 5;
    const int ch = warp & 1, rg = warp >> 1;
    constexpr int RPW = M / 4;
    const int rbase = rg * RPW;
    for (int nt = 0; nt < 4; ++nt) {
        unsigned long long acc[RPW][2];
#pragma unroll
        for (int rr = 0; rr < RPW; ++rr) { acc[rr][0] = 0ull; acc[rr][1] = 0ull; }
        for (int kt = 0; kt < 16; ++kt) {
            __syncthreads();
#pragma unroll
            for (int s = 0; s < 4; ++s) {
                int idx = tid + s * 256;
                int c = idx >> 3, k4 = (idx & 7) * 4;
                float4 w = *(const float4*)&Wg[(nt * 128 + c) * wstride + kt * 32 + k4];
                *(float4*)&wt[c * 36 + k4] = w;
            }
            __syncthreads();
            const float* inb = in + kt * 32;
#pragma unroll
            for (int kk = 0; kk < 32; kk += 4) {
                unsigned long long w01[2], w23[2];
#pragma unroll
                for (int cc = 0; cc < 2; ++cc) {
                    int cl = ch * 64 + cc * 32 + lane;
                    float4 w = *(const float4*)&wt[cl * 36 + kk];
                    w01[cc] = pack2(w.x, w.y);
                    w23[cc] = pack2(w.z, w.w);
                }
#pragma unroll
                for (int rr = 0; rr < RPW; ++rr) {
                    float4 a = *(const float4*)&inb[(rbase + rr) * 512 + kk];
                    unsigned long long a01 = pack2(a.x, a.y);
                    unsigned long long a23 = pack2(a.z, a.w);
#pragma unroll
                    for (int cc = 0; cc < 2; ++cc) {
                        ffma2(acc[rr][cc], a01, w01[cc]);
                        ffma2(acc[rr][cc], a23, w23[cc]);
                    }
                }
            }
        }
#pragma unroll
        for (int cc = 0; cc < 2; ++cc) {
            int c = nt * 128 + ch * 64 + cc * 32 + lane;
            float bval = BIAS ? bias[c] : 0.0f;
#pragma unroll
            for (int rr = 0; rr < RPW; ++rr) {
                float2 s = unpack2(acc[rr][cc]);
                float r = s.x + s.y + bval;
                if (RELU) r = fmaxf(r, 0.0f);
                out[(rbase + rr) * ostride + c] = r;
            }
        }
    }
}

__global__ void __launch_bounds__(256, 1)
stage1_kernel(const float* __restrict__ brick, const float* __restrict__ xy,
              const float* __restrict__ Wxy, const float* __restrict__ bxy,
              const float* __restrict__ Wa, const float* __restrict__ ba,
              const float* __restrict__ Wb, const float* __restrict__ bb,
              const float* __restrict__ Wca) {
    float* sm = (float*)s_raw;
    float* A = sm;
    float* Bm = sm + 8 * 512;
    float* wt = sm + 16 * 512;
    const int r0 = blockIdx.x * 8;
    for (int idx = threadIdx.x; idx < 8 * 128; idx += 256) {
        int m = idx >> 7, q = idx & 127;
        *(float4*)&A[m * 512 + q * 4] =
            *(const float4*)&brick[(size_t)(r0 + m) * 512 + q * 4];
    }
    layer512<8, false, true>(A, Wa, 512, ba, Bm, 512, wt);
    __syncthreads();
    for (int idx = threadIdx.x; idx < 8 * 512; idx += 256) {
        int m = idx >> 9, h = idx & 511;
        float x0 = xy[(r0 + m) * 2 + 0];
        float x1 = xy[(r0 + m) * 2 + 1];
        float val = Bm[idx] + x0 * Wxy[h * 2 + 0] + x1 * Wxy[h * 2 + 1] + bxy[h];
        Bm[idx] = fmaxf(val, 0.0f);
    }
    layer512<8, true, true>(Bm, Wb, 512, bb, A, 512, wt);
    layer512<8, false, false>(A, Wca, 1024, nullptr, g_u + r0 * 512, 512, wt);
    layer512<8, false, false>(A, Wca + 512, 1024, nullptr, g_v + r0 * 512, 512, wt);
}

// ---------------- prep: split + permute weights ----------------------------
__global__ void prep_kernel(const float* __restrict__ Wcb,
                            const float* __restrict__ Wcc) {
    int gid = blockIdx.x * 256 + threadIdx.x;   // 65536 threads
    for (int e = gid; e < 262144; e += 65536) {
        int n = e >> 9, k = e & 511;
        uint32_t dst = prow(n, k >> 3) + (uint32_t)((k & 7) * 2);
        {
            float v = Wcb[e];
            __nv_bfloat16 h = __float2bfloat16(v);
            __nv_bfloat16 l = __float2bfloat16(v - __bfloat162float(h));
            *(__nv_bfloat16*)(g_wcb_hi + dst) = h;
            *(__nv_bfloat16*)(g_wcb_lo + dst) = l;
        }
        {
            float v = Wcc[e];
            __nv_bfloat16 h = __float2bfloat16(v);
            __nv_bfloat16 l = __float2bfloat16(v - __bfloat162float(h));
            *(__nv_bfloat16*)(g_wcc_hi + dst) = h;
            *(__nv_bfloat16*)(g_wcc_lo + dst) = l;
        }
    }
}

// ---------------- layer kernels (mma.sync) ---------------------------------
// smem: A_hi 0..64K, A_lo 64K..128K, Wbuf[2] (hi 16K + lo 16K each) 128K..192K,
//       Wout 192K..196K, red 196K..198K
#define SM_A_HI  0
#define SM_A_LO  65536
#define SM_WB(b) (131072 + (b) * 32768)
#define SM_WOUT  196608
#define SM_RED   200704
#define SMEM_BYTES 202752

template <int LAYER>
__global__ void __launch_bounds__(256, 1)
layer_kernel(const float* __restrict__ bca, const float* __restrict__ bias,
             const float* __restrict__ Wout, const float* __restrict__ bout,
             float* __restrict__ out) {
    char* sm = s_raw;
    const uint32_t smem = smem_u32(sm);
    const int tid = threadIdx.x, wid = tid >> 5, lane = tid & 31;
    const int tile = blockIdx.x;
    const int wm = wid & 1;          // M half (32 rows)
    const int wn = wid >> 1;         // N quarter (32 cols of 128-chunk)

    const char* whi = (LAYER == 1) ? g_wcb_hi : g_wcc_hi;
    const char* wlo = (LAYER == 1) ? g_wcb_lo : g_wcc_lo;

    // -- prologue: W piece (nc=0,kc=0) async; A tile build/load --
    {
        // piece q=0: rows 0..127 of W, kbytes 0..127
#pragma unroll
        for (int s = 0; s < 4; ++s) {
            int g2 = tid + s * 256;           // 1024 granules per version
            int nrow = g2 >> 3, c = g2 & 7;
            const char* srch = whi + nrow * 1024 + c * 16;
            const char* srcl = wlo + nrow * 1024 + c * 16;
            cp16(smem + SM_WB(0) + nrow * 128 + c * 16, srch);
            cp16(smem + SM_WB(0) + 16384 + nrow * 128 + c * 16, srcl);
        }
        if (LAYER == 2) {
            // A tile linear copy from e1 blobs (64KB each)
            const char* srch = g_e1_hi + (size_t)tile * 65536;
            const char* srcl = g_e1_lo + (size_t)tile * 65536;
#pragma unroll
            for (int s = 0; s < 16; ++s) {
                int o = (tid + s * 256) * 16;
                cp16(smem + SM_A_HI + o, srch + o);
                cp16(smem + SM_A_LO + o, srcl + o);
            }
            // Wout -> smem (1024 floats)
            for (int q = tid; q < 256; q += 256)
                *(float4*)(sm + SM_WOUT + q * 16) = *(const float4*)&Wout[q * 4];
        }
        cp_commit();
    }
    if (LAYER == 1) {
        // build e0 tile: row r = tid>>2, chunks (tid&3)*16 + s
        const int p0 = tile * TILE_M;
        const int b = p0 / 36864;
        const int rem = p0 - b * 36864;
        const int i = rem / 192, j0 = rem - i * 192;
        const int r = tid >> 2;
        const float* up = g_u + (size_t)(b * 192 + j0 + r) * HD;
        const float* vp = g_v + (size_t)(b * 192 + i) * HD;
        const int cb = (tid & 3) * 16;
#pragma unroll
        for (int s = 0; s < 16; ++s) {
            int chunk = cb + s, k0 = chunk * 8;
            float4 u0 = *(const float4*)(up + k0);
            float4 u1 = *(const float4*)(up + k0 + 4);
            float4 v0 = *(const float4*)(vp + k0);
            float4 v1 = *(const float4*)(vp + k0 + 4);
            float4 c0 = *(const float4*)(bca + k0);
            float4 c1 = *(const float4*)(bca + k0 + 4);
            float x[8] = {u0.x + v0.x + c0.x, u0.y + v0.y + c0.y,
                          u0.z + v0.z + c0.z, u0.w + v0.w + c0.w,
                          u1.x + v1.x + c1.x, u1.y + v1.y + c1.y,
                          u1.z + v1.z + c1.z, u1.w + v1.w + c1.w};
            uint32_t hi4[4], lo4[4];
#pragma unroll
            for (int t = 0; t < 4; ++t) {
                float a0 = fmaxf(x[2 * t], 0.0f);
                float a1 = fmaxf(x[2 * t + 1], 0.0f);
                __nv_bfloat16 h0 = __float2bfloat16(a0);
                __nv_bfloat16 h1 = __float2bfloat16(a1);
                __nv_bfloat16 l0 = __float2bfloat16(a0 - __bfloat162float(h0));
                __nv_bfloat16 l1 = __float2bfloat16(a1 - __bfloat162float(h1));
                hi4[t] = pkbf(h0, h1);
                lo4[t] = pkbf(l0, l1);
            }
            uint32_t off = prow(r, chunk);
            *(uint4*)(sm + SM_A_HI + off) = make_uint4(hi4[0], hi4[1], hi4[2], hi4[3]);
            *(uint4*)(sm + SM_A_LO + off) = make_uint4(lo4[0], lo4[1], lo4[2], lo4[3]);
        }
    }

    // lane constants for ldmatrix addressing
    const int a_row = wm * 32 + (lane & 15);
    const int a_half = lane >> 4;
    const int w_rl = (lane & 7) + ((lane >> 4) << 3);  // row within n16 tile
    const int w_half = (lane >> 3) & 1;

    float head[2][2][2];                     // [mt][rhalf][o] (layer2)
#pragma unroll
    for (int a2 = 0; a2 < 2; ++a2)
#pragma unroll
        for (int b2 = 0; b2 < 2; ++b2) { head[a2][b2][0] = 0.f; head[a2][b2][1] = 0.f; }

    float acc[2][4][4];

    for (int q = 0; q < 32; ++q) {
        const int nc = q >> 3, kc = q & 7, buf = q & 1;
        // prefetch next piece
        if (q + 1 < 32) {
            int qn = q + 1, ncn = qn >> 3, kcn = qn & 7;
            const char* bh = whi + (size_t)ncn * 128 * 1024 + kcn * 128;
            const char* bl = wlo + (size_t)ncn * 128 * 1024 + kcn * 128;
            uint32_t db = smem + SM_WB(buf ^ 1);
#pragma unroll
            for (int s = 0; s < 4; ++s) {
                int g2 = tid + s * 256;
                int nrow = g2 >> 3, c = g2 & 7;
                cp16(db + nrow * 128 + c * 16, bh + nrow * 1024 + c * 16);
                cp16(db + 16384 + nrow * 128 + c * 16, bl + nrow * 1024 + c * 16);
            }
            cp_commit();
            cp_wait1();
        } else {
            cp_wait0();
        }
        __syncthreads();

        if (kc == 0) {
#pragma unroll
            for (int mt = 0; mt < 2; ++mt)
#pragma unroll
                for (int nt = 0; nt < 4; ++nt)
#pragma unroll
                    for (int e = 0; e < 4; ++e) acc[mt][nt][e] = 0.f;
        }

        const uint32_t wbh = smem + SM_WB(buf);
        const uint32_t wbl = wbh + 16384;
#pragma unroll
        for (int k16 = 0; k16 < 4; ++k16) {
            uint32_t ah[2][4], al[2][4], wh[2][4], wl[2][4];
            const int achunk = kc * 8 + k16 * 2 + a_half;
#pragma unroll
            for (int mt = 0; mt < 2; ++mt) {
                int row = a_row + mt * 16;
                uint32_t off = prow(row, achunk);
                ldsm_x4(ah[mt], smem + SM_A_HI + off);
                ldsm_x4(al[mt], smem + SM_A_LO + off);
            }
#pragma unroll
            for (int nt = 0; nt < 2; ++nt) {
                int rl = wn * 32 + nt * 16 + w_rl;
                int chunk = k16 * 2 + w_half;
                uint32_t off = (uint32_t)(rl * 128 + ((chunk ^ (rl & 7)) << 4));
                ldsm_x4(wh[nt], wbh + off);
                ldsm_x4(wl[nt], wbl + off);
            }
#pragma unroll
            for (int mt = 0; mt < 2; ++mt)
#pragma unroll
                for (int n8 = 0; n8 < 4; ++n8) {
                    const uint32_t* bh2 = &wh[n8 >> 1][(n8 & 1) * 2];
                    const uint32_t* bl2 = &wl[n8 >> 1][(n8 & 1) * 2];
                    mma16816(acc[mt][n8], ah[mt], bh2);
                    mma16816(acc[mt][n8], al[mt], bh2);
                    mma16816(acc[mt][n8], ah[mt], bl2);
                }
        }

        if (kc == 7) {
            // epilogue for this nc
#pragma unroll
            for (int mt = 0; mt < 2; ++mt)
#pragma unroll
                for (int n8 = 0; n8 < 4; ++n8)
#pragma unroll
                    for (int rh = 0; rh < 2; ++rh) {
                        int row = wm * 32 + mt * 16 + (lane >> 2) + rh * 8;
                        int col = nc * 128 + wn * 32 + n8 * 8 + (lane & 3) * 2;
                        float v0 = acc[mt][n8][rh * 2 + 0] + bias[col];
                        float v1 = acc[mt][n8][rh * 2 + 1] + bias[col + 1];
                        v0 = fmaxf(v0, 0.0f);
                        v1 = fmaxf(v1, 0.0f);
                        if (LAYER == 1) {
                            __nv_bfloat16 h0 = __float2bfloat16(v0);
                            __nv_bfloat16 h1 = __float2bfloat16(v1);
                            __nv_bfloat16 l0 = __float2bfloat16(v0 - __bfloat162float(h0));
                            __nv_bfloat16 l1 = __float2bfloat16(v1 - __bfloat162float(h1));
                            int chunk = col >> 3;           // 8 cols per 16B
                            uint32_t off = prow(row, chunk) + (uint32_t)((col & 7) * 2);
                            size_t dst = (size_t)tile * 65536 + off;
                            *(uint32_t*)(g_e1_hi + dst) = pkbf(h0, h1);
                            *(uint32_t*)(g_e1_lo + dst) = pkbf(l0, l1);
                        } else {
                            const float* wo = (const float*)(sm + SM_WOUT);
                            head[mt][rh][0] = fmaf(v0, wo[col], head[mt][rh][0]);
                            head[mt][rh][0] = fmaf(v1, wo[col + 1], head[mt][rh][0]);
                            head[mt][rh][1] = fmaf(v0, wo[512 + col], head[mt][rh][1]);
                            head[mt][rh][1] = fmaf(v1, wo[512 + col + 1], head[mt][rh][1]);
                        }
                    }
        }
        __syncthreads();   // protect W buffer before reuse
    }

    if (LAYER == 2) {
        float* red = (float*)(sm + SM_RED);   // [wn][64][2]
#pragma unroll
        for (int mt = 0; mt < 2; ++mt)
#pragma unroll
            for (int rh = 0; rh < 2; ++rh)
#pragma unroll
                for (int o = 0; o < 2; ++o) {
                    float s = head[mt][rh][o];
                    s += __shfl_xor_sync(0xffffffffu, s, 1);
                    s += __shfl_xor_sync(0xffffffffu, s, 2);
                    if ((lane & 3) == 0) {
                        int row = wm * 32 + mt * 16 + (lane >> 2) + rh * 8;
                        red[wn * 128 + row * 2 + o] = s;
                    }
                }
        __syncthreads();
        if (tid < 128) {
            int row = tid >> 1, o = tid & 1;
            float s = red[row * 2 + o] + red[128 + row * 2 + o] +
                      red[256 + row * 2 + o] + red[384 + row * 2 + o] + bout[o];
            size_t p = (size_t)tile * TILE_M + row;
            out[p * 2 + o] = s;
        }
    }
}

// ---------------------------------------------------------------------------
extern "C" void kernel_launch(void* const* d_in, const int* in_sizes, int n_in,
                              void* d_out, int out_size) {
    const float* brick = (const float*)d_in[0];
    const float* xy    = (const float*)d_in[1];
    const float* Wxy   = (const float*)d_in[2];
    const float* bxy   = (const float*)d_in[3];
    const float* Wa    = (const float*)d_in[4];
    const float* ba    = (const float*)d_in[5];
    const float* Wb    = (const float*)d_in[6];
    const float* bb    = (const float*)d_in[7];
    const float* Wca   = (const float*)d_in[8];
    const float* bca   = (const float*)d_in[9];
    const float* Wcb   = (const float*)d_in[10];
    const float* bcb   = (const float*)d_in[11];
    const float* Wcc   = (const float*)d_in[12];
    const float* bcc   = (const float*)d_in[13];
    const float* Wout  = (const float*)d_in[14];
    const float* bout  = (const float*)d_in[15];
    float* out = (float*)d_out;

    const size_t s1 = (size_t)(8 * 512 + 8 * 512 + 128 * 36) * sizeof(float);
    cudaFuncSetAttribute(stage1_kernel,
                         cudaFuncAttributeMaxDynamicSharedMemorySize, (int)s1);
    cudaFuncSetAttribute(layer_kernel<1>,
                         cudaFuncAttributeMaxDynamicSharedMemorySize, SMEM_BYTES);
    cudaFuncSetAttribute(layer_kernel<2>,
                         cudaFuncAttributeMaxDynamicSharedMemorySize, SMEM_BYTES);

    stage1_kernel<<<96, 256, s1>>>(brick, xy, Wxy, bxy, Wa, ba, Wb, bb, Wca);
    prep_kernel<<<256, 256>>>(Wcb, Wcc);
    layer_kernel<1><<<N_TILES2, 256, SMEM_BYTES>>>(bca, bcb, nullptr, nullptr, nullptr);
    layer_kernel<2><<<N_TILES2, 256, SMEM_BYTES>>>(bca, bcc, Wout, bout, out);
}

// round 8
// speedup vs baseline: 3.9759x; 1.3288x over previous
#include <cuda_runtime.h>
#include <cuda_fp16.h>
#include <cstdint>

// ===========================================================================
// BrickVectorEdgeModel — mma.sync fp16 2-term split
//   stage1 (SIMT fp32): u, v
//   prep:   Wcb/Wcc -> fp16 (hi only), permuted 32KB piece blobs
//   layer1: e0 = relu(v_i + u_j + b_ca) built in smem (fp16 hi/lo);
//           e1 = relu(e0@Wcb^T + b_cb) via mma.sync (Ah*W + Al*W) ->
//           global permuted hi/lo fp16 blobs
//   layer2: e2 = relu(e1@Wcc^T + b_cc) via mma.sync; fused @W_out + b_out
// Error budget: dropped term A*W_lo ~ 2^-12 -> predicted rel_err ~4e-4.
// ===========================================================================

#define HD 512
#define TILE_M 64
#define N_TILES2 2304          // 147456 / 64

__device__ float g_u[768 * HD];
__device__ float g_v[768 * HD];
__device__ char  g_wcb_h[524288];      // 512x512 fp16, piece-blob layout
__device__ char  g_wcc_h[524288];
__device__ char  g_e1_hi[150994944];   // 2304 tiles * 64 rows * 1024B
__device__ char  g_e1_lo[150994944];

extern __shared__ char s_raw[];

// ---------------- PTX helpers ----------------------------------------------
__device__ __forceinline__ uint32_t smem_u32(const void* p) {
    uint32_t a;
    asm("{ .reg .u64 t; cvta.to.shared.u64 t, %1; cvt.u32.u64 %0, t; }"
        : "=r"(a) : "l"(p));
    return a;
}
__device__ __forceinline__ void cp16(uint32_t d, const void* s) {
    asm volatile("cp.async.cg.shared.global [%0], [%1], 16;" :: "r"(d), "l"(s));
}
__device__ __forceinline__ void cp_commit() { asm volatile("cp.async.commit_group;"); }
__device__ __forceinline__ void cp_wait1()  { asm volatile("cp.async.wait_group 1;"); }
__device__ __forceinline__ void cp_wait0()  { asm volatile("cp.async.wait_group 0;"); }

__device__ __forceinline__ void ldsm_x4(uint32_t* r, uint32_t a) {
    asm volatile("ldmatrix.sync.aligned.m8n8.x4.shared.b16 {%0,%1,%2,%3}, [%4];"
                 : "=r"(r[0]), "=r"(r[1]), "=r"(r[2]), "=r"(r[3]) : "r"(a));
}
__device__ __forceinline__ void mma16816(float* d, const uint32_t* a,
                                         const uint32_t* b) {
    asm volatile("mma.sync.aligned.m16n8k16.row.col.f32.f16.f16.f32 "
                 "{%0,%1,%2,%3}, {%4,%5,%6,%7}, {%8,%9}, {%0,%1,%2,%3};"
                 : "+f"(d[0]), "+f"(d[1]), "+f"(d[2]), "+f"(d[3])
                 : "r"(a[0]), "r"(a[1]), "r"(a[2]), "r"(a[3]),
                   "r"(b[0]), "r"(b[1]));
}
__device__ __forceinline__ uint32_t pkh(__half a, __half b) {
    return (uint32_t)__half_as_ushort(a) |
           ((uint32_t)__half_as_ushort(b) << 16);
}

// A-tile permuted row layout: 1024B rows, 16B chunks, chunk ^= (row & 7)
__device__ __forceinline__ uint32_t prow(int row, int chunk) {
    return (uint32_t)(row * 1024 + ((chunk ^ (row & 7)) << 4));
}

// ---------------- stage 1: SIMT fp32 (validated) ---------------------------
__device__ __forceinline__ unsigned long long pack2(float x, float y) {
    unsigned long long r;
    asm("mov.b64 %0, {%1, %2};" : "=l"(r) : "f"(x), "f"(y));
    return r;
}
__device__ __forceinline__ void ffma2(unsigned long long& d,
                                      unsigned long long a, unsigned long long b) {
    asm("fma.rn.f32x2 %0, %1, %2, %0;" : "+l"(d) : "l"(a), "l"(b));
}
__device__ __forceinline__ float2 unpack2(unsigned long long v) {
    float2 f;
    asm("mov.b64 {%0, %1}, %2;" : "=f"(f.x), "=f"(f.y) : "l"(v));
    return f;
}

template <int M, bool RELU, bool BIAS>
__device__ __forceinline__ void layer512(const float* __restrict__ in,
                                         const float* __restrict__ Wg, int wstride,
                                         const float* __restrict__ bias,
                                         float* __restrict__ out, int ostride,
                                         float* __restrict__ wt) {
    const int tid = threadIdx.x, lane = tid & 31, warp = tid >> 5;
    const int ch = warp & 1, rg = warp >> 1;
    constexpr int RPW = M / 4;
    const int rbase = rg * RPW;
    for (int nt = 0; nt < 4; ++nt) {
        unsigned long long acc[RPW][2];
#pragma unroll
        for (int rr = 0; rr < RPW; ++rr) { acc[rr][0] = 0ull; acc[rr][1] = 0ull; }
        for (int kt = 0; kt < 16; ++kt) {
            __syncthreads();
#pragma unroll
            for (int s = 0; s < 4; ++s) {
                int idx = tid + s * 256;
                int c = idx >> 3, k4 = (idx & 7) * 4;
                float4 w = *(const float4*)&Wg[(nt * 128 + c) * wstride + kt * 32 + k4];
                *(float4*)&wt[c * 36 + k4] = w;
            }
            __syncthreads();
            const float* inb = in + kt * 32;
#pragma unroll
            for (int kk = 0; kk < 32; kk += 4) {
                unsigned long long w01[2], w23[2];
#pragma unroll
                for (int cc = 0; cc < 2; ++cc) {
                    int cl = ch * 64 + cc * 32 + lane;
                    float4 w = *(const float4*)&wt[cl * 36 + kk];
                    w01[cc] = pack2(w.x, w.y);
                    w23[cc] = pack2(w.z, w.w);
                }
#pragma unroll
                for (int rr = 0; rr < RPW; ++rr) {
                    float4 a = *(const float4*)&inb[(rbase + rr) * 512 + kk];
                    unsigned long long a01 = pack2(a.x, a.y);
                    unsigned long long a23 = pack2(a.z, a.w);
#pragma unroll
                    for (int cc = 0; cc < 2; ++cc) {
                        ffma2(acc[rr][cc], a01, w01[cc]);
                        ffma2(acc[rr][cc], a23, w23[cc]);
                    }
                }
            }
        }
#pragma unroll
        for (int cc = 0; cc < 2; ++cc) {
            int c = nt * 128 + ch * 64 + cc * 32 + lane;
            float bval = BIAS ? bias[c] : 0.0f;
#pragma unroll
            for (int rr = 0; rr < RPW; ++rr) {
                float2 s = unpack2(acc[rr][cc]);
                float r = s.x + s.y + bval;
                if (RELU) r = fmaxf(r, 0.0f);
                out[(rbase + rr) * ostride + c] = r;
            }
        }
    }
}

__global__ void __launch_bounds__(256, 1)
stage1_kernel(const float* __restrict__ brick, const float* __restrict__ xy,
              const float* __restrict__ Wxy, const float* __restrict__ bxy,
              const float* __restrict__ Wa, const float* __restrict__ ba,
              const float* __restrict__ Wb, const float* __restrict__ bb,
              const float* __restrict__ Wca) {
    float* sm = (float*)s_raw;
    float* A = sm;
    float* Bm = sm + 8 * 512;
    float* wt = sm + 16 * 512;
    const int r0 = blockIdx.x * 8;
    for (int idx = threadIdx.x; idx < 8 * 128; idx += 256) {
        int m = idx >> 7, q = idx & 127;
        *(float4*)&A[m * 512 + q * 4] =
            *(const float4*)&brick[(size_t)(r0 + m) * 512 + q * 4];
    }
    layer512<8, false, true>(A, Wa, 512, ba, Bm, 512, wt);
    __syncthreads();
    for (int idx = threadIdx.x; idx < 8 * 512; idx += 256) {
        int m = idx >> 9, h = idx & 511;
        float x0 = xy[(r0 + m) * 2 + 0];
        float x1 = xy[(r0 + m) * 2 + 1];
        float val = Bm[idx] + x0 * Wxy[h * 2 + 0] + x1 * Wxy[h * 2 + 1] + bxy[h];
        Bm[idx] = fmaxf(val, 0.0f);
    }
    layer512<8, true, true>(Bm, Wb, 512, bb, A, 512, wt);
    layer512<8, false, false>(A, Wca, 1024, nullptr, g_u + r0 * 512, 512, wt);
    layer512<8, false, false>(A, Wca + 512, 1024, nullptr, g_v + r0 * 512, 512, wt);
}

// ---------------- prep: fp16-convert + permute weights ---------------------
// piece p = nc*4 + kq (32KB): rows r=0..127 (n = nc*128+r), k = kq*128..+128.
// within piece: row stride 256B, chunk c=0..15, stored at ((c^(r&7))<<4).
__global__ void prep_kernel(const float* __restrict__ Wcb,
                            const float* __restrict__ Wcc) {
    int gid = blockIdx.x * 256 + threadIdx.x;   // 65536 threads
    for (int e = gid; e < 262144; e += 65536) {
        int n = e >> 9, k = e & 511;
        int nc = n >> 7, r = n & 127, kq = k >> 7, kk = k & 127;
        int c = kk >> 3, w = kk & 7;
        uint32_t dst = (uint32_t)((nc * 4 + kq) * 32768 + r * 256 +
                                  ((c ^ (r & 7)) << 4) + w * 2);
        *(__half*)(g_wcb_h + dst) = __float2half_rn(Wcb[e]);
        *(__half*)(g_wcc_h + dst) = __float2half_rn(Wcc[e]);
    }
}

// ---------------- layer kernels (mma.sync, fp16 2-term) --------------------
// smem: A_hi 0..64K, A_lo 64..128K, Wbuf[2] 32K each 128..192K,
//       Wout 192..196K, red 196..198K
#define SM_A_HI  0
#define SM_A_LO  65536
#define SM_WB(b) (131072 + (b) * 32768)
#define SM_WOUT  196608
#define SM_RED   200704
#define SMEM_BYTES 202752

template <int LAYER>
__global__ void __launch_bounds__(256, 1)
layer_kernel(const float* __restrict__ bca, const float* __restrict__ bias,
             const float* __restrict__ Wout, const float* __restrict__ bout,
             float* __restrict__ out) {
    char* sm = s_raw;
    const uint32_t smem = smem_u32(sm);
    const int tid = threadIdx.x, wid = tid >> 5, lane = tid & 31;
    const int tile = blockIdx.x;
    const int wm = wid & 1;          // M half (32 rows)
    const int wn = wid >> 1;         // N quarter (32 cols of 128-chunk)

    const char* wsrc = (LAYER == 1) ? g_wcb_h : g_wcc_h;

    // -- prologue: W piece 0 (32KB) async; layer2 also A tile (128KB) --
    {
#pragma unroll
        for (int s = 0; s < 8; ++s) {
            int g2 = tid + s * 256;          // 2048 granules
            cp16(smem + SM_WB(0) + g2 * 16, wsrc + g2 * 16);
        }
        if (LAYER == 2) {
            const char* srch = g_e1_hi + (size_t)tile * 65536;
            const char* srcl = g_e1_lo + (size_t)tile * 65536;
#pragma unroll
            for (int s = 0; s < 16; ++s) {
                int o = (tid + s * 256) * 16;
                cp16(smem + SM_A_HI + o, srch + o);
                cp16(smem + SM_A_LO + o, srcl + o);
            }
            for (int q = tid; q < 256; q += 256)
                *(float4*)(sm + SM_WOUT + q * 16) = *(const float4*)&Wout[q * 4];
        }
        cp_commit();
    }
    if (LAYER == 1) {
        // build e0 tile (fp16 hi/lo): row r = tid>>2, chunks (tid&3)*16 + s
        const int p0 = tile * TILE_M;
        const int b = p0 / 36864;
        const int rem = p0 - b * 36864;
        const int i = rem / 192, j0 = rem - i * 192;
        const int r = tid >> 2;
        const float* up = g_u + (size_t)(b * 192 + j0 + r) * HD;
        const float* vp = g_v + (size_t)(b * 192 + i) * HD;
        const int cb = (tid & 3) * 16;
#pragma unroll
        for (int s = 0; s < 16; ++s) {
            int chunk = cb + s, k0 = chunk * 8;
            float4 u0 = *(const float4*)(up + k0);
            float4 u1 = *(const float4*)(up + k0 + 4);
            float4 v0 = *(const float4*)(vp + k0);
            float4 v1 = *(const float4*)(vp + k0 + 4);
            float4 c0 = *(const float4*)(bca + k0);
            float4 c1 = *(const float4*)(bca + k0 + 4);
            float x[8] = {u0.x + v0.x + c0.x, u0.y + v0.y + c0.y,
                          u0.z + v0.z + c0.z, u0.w + v0.w + c0.w,
                          u1.x + v1.x + c1.x, u1.y + v1.y + c1.y,
                          u1.z + v1.z + c1.z, u1.w + v1.w + c1.w};
            uint32_t hi4[4], lo4[4];
#pragma unroll
            for (int t = 0; t < 4; ++t) {
                float a0 = fmaxf(x[2 * t], 0.0f);
                float a1 = fmaxf(x[2 * t + 1], 0.0f);
                __half h0 = __float2half_rn(a0);
                __half h1 = __float2half_rn(a1);
                __half l0 = __float2half_rn(a0 - __half2float(h0));
                __half l1 = __float2half_rn(a1 - __half2float(h1));
                hi4[t] = pkh(h0, h1);
                lo4[t] = pkh(l0, l1);
            }
            uint32_t off = prow(r, chunk);
            *(uint4*)(sm + SM_A_HI + off) = make_uint4(hi4[0], hi4[1], hi4[2], hi4[3]);
            *(uint4*)(sm + SM_A_LO + off) = make_uint4(lo4[0], lo4[1], lo4[2], lo4[3]);
        }
    }

    // lane constants for ldmatrix addressing
    const int a_row = wm * 32 + (lane & 15);
    const int a_half = lane >> 4;
    const int w_rl = (lane & 7) + ((lane >> 4) << 3);
    const int w_half = (lane >> 3) & 1;

    float head[2][2][2];
#pragma unroll
    for (int a2 = 0; a2 < 2; ++a2)
#pragma unroll
        for (int b2 = 0; b2 < 2; ++b2) { head[a2][b2][0] = 0.f; head[a2][b2][1] = 0.f; }

    float acc[2][4][4];

    for (int q = 0; q < 16; ++q) {          // nc = q>>2, kq = q&3 (128 k each)
        const int nc = q >> 2, kq = q & 3, buf = q & 1;
        if (q + 1 < 16) {
            const char* src = wsrc + (size_t)(q + 1) * 32768;
            uint32_t db = smem + SM_WB(buf ^ 1);
#pragma unroll
            for (int s = 0; s < 8; ++s) {
                int g2 = tid + s * 256;
                cp16(db + g2 * 16, src + g2 * 16);
            }
            cp_commit();
            cp_wait1();
        } else {
            cp_wait0();
        }
        __syncthreads();

        if (kq == 0) {
#pragma unroll
            for (int mt = 0; mt < 2; ++mt)
#pragma unroll
                for (int nt = 0; nt < 4; ++nt)
#pragma unroll
                    for (int e = 0; e < 4; ++e) acc[mt][nt][e] = 0.f;
        }

        const uint32_t wb = smem + SM_WB(buf);
#pragma unroll
        for (int k16 = 0; k16 < 8; ++k16) {
            uint32_t ah[2][4], al[2][4], wh[2][4];
            const int achunk = kq * 16 + k16 * 2 + a_half;
#pragma unroll
            for (int mt = 0; mt < 2; ++mt) {
                int row = a_row + mt * 16;
                uint32_t off = prow(row, achunk);
                ldsm_x4(ah[mt], smem + SM_A_HI + off);
                ldsm_x4(al[mt], smem + SM_A_LO + off);
            }
#pragma unroll
            for (int nt = 0; nt < 2; ++nt) {
                int rl = wn * 32 + nt * 16 + w_rl;
                int cc = k16 * 2 + w_half;
                uint32_t off = (uint32_t)(rl * 256 + (((cc) ^ (rl & 7)) << 4));
                ldsm_x4(wh[nt], wb + off);
            }
#pragma unroll
            for (int mt = 0; mt < 2; ++mt)
#pragma unroll
                for (int n8 = 0; n8 < 4; ++n8) {
                    const uint32_t* b2 = &wh[n8 >> 1][(n8 & 1) * 2];
                    mma16816(acc[mt][n8], ah[mt], b2);
                    mma16816(acc[mt][n8], al[mt], b2);
                }
        }

        if (kq == 3) {
            // epilogue for this nc
#pragma unroll
            for (int mt = 0; mt < 2; ++mt)
#pragma unroll
                for (int n8 = 0; n8 < 4; ++n8)
#pragma unroll
                    for (int rh = 0; rh < 2; ++rh) {
                        int row = wm * 32 + mt * 16 + (lane >> 2) + rh * 8;
                        int col = nc * 128 + wn * 32 + n8 * 8 + (lane & 3) * 2;
                        float v0 = acc[mt][n8][rh * 2 + 0] + bias[col];
                        float v1 = acc[mt][n8][rh * 2 + 1] + bias[col + 1];
                        v0 = fmaxf(v0, 0.0f);
                        v1 = fmaxf(v1, 0.0f);
                        if (LAYER == 1) {
                            __half h0 = __float2half_rn(v0);
                            __half h1 = __float2half_rn(v1);
                            __half l0 = __float2half_rn(v0 - __half2float(h0));
                            __half l1 = __float2half_rn(v1 - __half2float(h1));
                            int chunk = col >> 3;
                            uint32_t off = prow(row, chunk) + (uint32_t)((col & 7) * 2);
                            size_t dst = (size_t)tile * 65536 + off;
                            *(uint32_t*)(g_e1_hi + dst) = pkh(h0, h1);
                            *(uint32_t*)(g_e1_lo + dst) = pkh(l0, l1);
                        } else {
                            const float* wo = (const float*)(sm + SM_WOUT);
                            head[mt][rh][0] = fmaf(v0, wo[col], head[mt][rh][0]);
                            head[mt][rh][0] = fmaf(v1, wo[col + 1], head[mt][rh][0]);
                            head[mt][rh][1] = fmaf(v0, wo[512 + col], head[mt][rh][1]);
                            head[mt][rh][1] = fmaf(v1, wo[512 + col + 1], head[mt][rh][1]);
                        }
                    }
        }
        __syncthreads();
    }

    if (LAYER == 2) {
        float* red = (float*)(sm + SM_RED);
#pragma unroll
        for (int mt = 0; mt < 2; ++mt)
#pragma unroll
            for (int rh = 0; rh < 2; ++rh)
#pragma unroll
                for (int o = 0; o < 2; ++o) {
                    float s = head[mt][rh][o];
                    s += __shfl_xor_sync(0xffffffffu, s, 1);
                    s += __shfl_xor_sync(0xffffffffu, s, 2);
                    if ((lane & 3) == 0) {
                        int row = wm * 32 + mt * 16 + (lane >> 2) + rh * 8;
                        red[wn * 128 + row * 2 + o] = s;
                    }
                }
        __syncthreads();
        if (tid < 128) {
            int row = tid >> 1, o = tid & 1;
            float s = red[row * 2 + o] + red[128 + row * 2 + o] +
                      red[256 + row * 2 + o] + red[384 + row * 2 + o] + bout[o];
            size_t p = (size_t)tile * TILE_M + row;
            out[p * 2 + o] = s;
        }
    }
}

// ---------------------------------------------------------------------------
extern "C" void kernel_launch(void* const* d_in, const int* in_sizes, int n_in,
                              void* d_out, int out_size) {
    const float* brick = (const float*)d_in[0];
    const float* xy    = (const float*)d_in[1];
    const float* Wxy   = (const float*)d_in[2];
    const float* bxy   = (const float*)d_in[3];
    const float* Wa    = (const float*)d_in[4];
    const float* ba    = (const float*)d_in[5];
    const float* Wb    = (const float*)d_in[6];
    const float* bb    = (const float*)d_in[7];
    const float* Wca   = (const float*)d_in[8];
    const float* bca   = (const float*)d_in[9];
    const float* Wcb   = (const float*)d_in[10];
    const float* bcb   = (const float*)d_in[11];
    const float* Wcc   = (const float*)d_in[12];
    const float* bcc   = (const float*)d_in[13];
    const float* Wout  = (const float*)d_in[14];
    const float* bout  = (const float*)d_in[15];
    float* out = (float*)d_out;

    const size_t s1 = (size_t)(8 * 512 + 8 * 512 + 128 * 36) * sizeof(float);
    cudaFuncSetAttribute(stage1_kernel,
                         cudaFuncAttributeMaxDynamicSharedMemorySize, (int)s1);
    cudaFuncSetAttribute(layer_kernel<1>,
                         cudaFuncAttributeMaxDynamicSharedMemorySize, SMEM_BYTES);
    cudaFuncSetAttribute(layer_kernel<2>,
                         cudaFuncAttributeMaxDynamicSharedMemorySize, SMEM_BYTES);

    stage1_kernel<<<96, 256, s1>>>(brick, xy, Wxy, bxy, Wa, ba, Wb, bb, Wca);
    prep_kernel<<<256, 256>>>(Wcb, Wcc);
    layer_kernel<1><<<N_TILES2, 256, SMEM_BYTES>>>(bca, bcb, nullptr, nullptr, nullptr);
    layer_kernel<2><<<N_TILES2, 256, SMEM_BYTES>>>(bca, bcc, Wout, bout, out);
}